// round 8
// baseline (speedup 1.0000x reference)
#include <cuda_runtime.h>

#define BB    32
#define LMAX  64
#define EMB   512
#define DH    1024
#define G4    4096
#define NV    32000

// ---------------- device state (no allocation allowed) ----------------
__device__ float g_h[BB * DH];
__device__ float g_c[BB * DH];
__device__ float g_enc[BB * LMAX * DH];     // [b][l][d]
__device__ float g_e[BB * DH];              // decoder embedding of current token
__device__ float g_ctx[BB * DH];            // attention context
__device__ float g_inp[BB * DH];            // relu(comb) = LSTM x-input
__device__ float g_combP[8 * BB * DH];      // comb partial slabs (2 chunks x kSplit 4)
__device__ float g_gateP[4 * BB * G4];      // gate partial slabs (2 chunks x kSplit 2)
__device__ int   g_tok[BB];

// ---------------- f32x2 packed-FMA helpers ----------------
__device__ __forceinline__ unsigned long long pk2(float x, float y) {
    unsigned long long r;
    asm("mov.b64 %0, {%1, %2};" : "=l"(r) : "r"(__float_as_uint(x)), "r"(__float_as_uint(y)));
    return r;
}
__device__ __forceinline__ void upk2(unsigned long long v, float& lo, float& hi) {
    unsigned a, b;
    asm("mov.b64 {%0, %1}, %2;" : "=r"(a), "=r"(b) : "l"(v));
    lo = __uint_as_float(a); hi = __uint_as_float(b);
}
__device__ __forceinline__ unsigned long long ff2(unsigned long long a, unsigned long long b,
                                                  unsigned long long c) {
    unsigned long long d;
    asm("fma.rn.f32x2 %0, %1, %2, %3;" : "=l"(d) : "l"(a), "l"(b), "l"(c));
    return d;
}

// ---------------------------------------------------------------------
// Generic skinny GEMM: OUT[b][j] = sum_k IN[b][k] * W[k][j]  (32 rows)
// - gridDim.z selects chunk (two independent input/weight pairs)
// - gridDim.y = kSplit; each (z,kc) writes a partial slab (deterministic, no atomics)
// - input staged transposed in smem (pad 36 -> 16B aligned b-pairs)
// - per thread: 2 j columns x 8 batch rows, f32x2 accumulators over b-pairs
// - optional token-gather rows for chunk 0 (encoder embedding lookup)
// - bias added only in slab si==0
// ---------------------------------------------------------------------
extern "C" __global__ void __launch_bounds__(256)
linear32(const float* __restrict__ in0, long long in0Stride,
         const int* __restrict__ tok0, int tok0Stride, int K0,
         const float* __restrict__ W0,
         const float* __restrict__ in1, long long in1Stride, int K1,
         const float* __restrict__ W1,
         int N, const float* __restrict__ bias,
         float* __restrict__ out, long long outRowStride,
         long long outSlabStride, int kSplit)
{
    extern __shared__ float s_in[];

    const float* in; const float* W; const int* tok = nullptr;
    int tokStride = 0; long long inStride; int K;
    if (blockIdx.z == 0) { in = in0; W = W0; tok = tok0; tokStride = tok0Stride; inStride = in0Stride; K = K0; }
    else                 { in = in1; W = W1;                                     inStride = in1Stride; K = K1; }

    const int Kc  = K / kSplit;
    const int k0  = blockIdx.y * Kc;
    const int tid = threadIdx.x;

    // stage input slice transposed: s_in[k*36 + b]
    for (int idx = tid; idx < BB * Kc; idx += blockDim.x) {
        int b = idx / Kc;
        int k = idx - b * Kc;
        long long row = tok ? (long long)tok[b * tokStride] * inStride
                            : (long long)b * inStride;
        s_in[(unsigned)k * 36u + b] = in[row + k0 + k];
    }
    __syncthreads();

    const int half = blockDim.x >> 2;          // threads covering j dimension
    const int tj   = tid % half;
    const int bg   = tid / half;               // 0..3 -> 8 batch rows each
    const int b0   = bg * 8;
    const int jA   = blockIdx.x * (blockDim.x >> 1) + 2 * tj;

    const float* Wp = W + (long long)k0 * N + jA;
    const float* sp = s_in + b0;

    unsigned long long a00 = 0, a01 = 0, a02 = 0, a03 = 0;
    unsigned long long a10 = 0, a11 = 0, a12 = 0, a13 = 0;

#pragma unroll 4
    for (int k = 0; k < Kc; ++k) {
        float2 w = *reinterpret_cast<const float2*>(Wp);
        Wp += N;
        unsigned long long wa = pk2(w.x, w.x);
        unsigned long long wb = pk2(w.y, w.y);
        const ulonglong2* sr = reinterpret_cast<const ulonglong2*>(sp);
        ulonglong2 p0 = sr[0];     // b0..b0+3
        ulonglong2 p1 = sr[1];     // b0+4..b0+7
        a00 = ff2(p0.x, wa, a00);  a10 = ff2(p0.x, wb, a10);
        a01 = ff2(p0.y, wa, a01);  a11 = ff2(p0.y, wb, a11);
        a02 = ff2(p1.x, wa, a02);  a12 = ff2(p1.x, wb, a12);
        a03 = ff2(p1.y, wa, a03);  a13 = ff2(p1.y, wb, a13);
        sp += 36;
    }

    const int si = blockIdx.z * kSplit + blockIdx.y;
    float bj0 = 0.f, bj1 = 0.f;
    if (si == 0 && bias) { bj0 = bias[jA]; bj1 = bias[jA + 1]; }

    float* ob = out + (long long)si * outSlabStride;

    float xl, xh, yl, yh;
#define STORE_PAIR(ACC0, ACC1, BOFF)                                              \
    {                                                                             \
        upk2(ACC0, xl, xh); upk2(ACC1, yl, yh);                                   \
        *reinterpret_cast<float2*>(ob + (long long)(b0 + BOFF)     * outRowStride + jA) = \
            make_float2(xl + bj0, yl + bj1);                                      \
        *reinterpret_cast<float2*>(ob + (long long)(b0 + BOFF + 1) * outRowStride + jA) = \
            make_float2(xh + bj0, yh + bj1);                                      \
    }
    STORE_PAIR(a00, a10, 0)
    STORE_PAIR(a01, a11, 2)
    STORE_PAIR(a02, a12, 4)
    STORE_PAIR(a03, a13, 6)
#undef STORE_PAIR
}

// ---------------- LSTM pointwise: sum gate partials + bias, update h,c ----------------
extern "C" __global__ void lstm_kernel(const float* __restrict__ P,
                                       const float* __restrict__ bias,
                                       float* __restrict__ encOut, int nParts)
{
    int b = blockIdx.x, tid = threadIdx.x;
    for (int d = tid; d < DH; d += 256) {
        float gi = bias[d], gf = bias[DH + d], gg = bias[2 * DH + d], go = bias[3 * DH + d];
        for (int p = 0; p < nParts; ++p) {
            const float* pb = P + (long long)p * BB * G4 + (long long)b * G4;
            gi += pb[d]; gf += pb[DH + d]; gg += pb[2 * DH + d]; go += pb[3 * DH + d];
        }
        float iv = 1.f / (1.f + expf(-gi));
        float fv = 1.f / (1.f + expf(-gf));
        float gv = tanhf(gg);
        float ov = 1.f / (1.f + expf(-go));
        float cv = fv * g_c[b * DH + d] + iv * gv;
        float hv = ov * tanhf(cv);
        g_c[b * DH + d] = cv;
        g_h[b * DH + d] = hv;
        if (encOut) encOut[(long long)b * LMAX * DH + d] = hv;
    }
}

// ---------------- decoder: embed gather + attention softmax + context ----------------
extern "C" __global__ void attn_ctx(const float* __restrict__ dec_embed,
                                    const float* __restrict__ attn_w,
                                    const float* __restrict__ attn_b)
{
    __shared__ float se[DH], sh[DH], sp[4 * 64], sw[64];
    __shared__ float s_max, s_inv;
    int b = blockIdx.x, tid = threadIdx.x;
    int tk = g_tok[b];
    for (int d = tid; d < DH; d += 256) {
        float ev = dec_embed[(long long)tk * DH + d];
        se[d] = ev;
        g_e[b * DH + d] = ev;
        sh[d] = g_h[b * DH + d];
    }
    __syncthreads();
    {
        int l = tid & 63, q = tid >> 6;                    // 4 k-quarters of 512
        const float* src = (q < 2) ? (se + q * 512) : (sh + (q - 2) * 512);
        const float* wp  = attn_w + (long long)(q * 512) * 64 + l;
        float a = 0.f;
#pragma unroll 8
        for (int kk = 0; kk < 512; ++kk) a += src[kk] * wp[(long long)kk * 64];
        sp[q * 64 + l] = a;
    }
    __syncthreads();
    if (tid < 64)
        sw[tid] = sp[tid] + sp[64 + tid] + sp[128 + tid] + sp[192 + tid] + attn_b[tid];
    __syncthreads();
    if (tid == 0) {
        float m = sw[0];
        for (int l = 1; l < 64; ++l) m = fmaxf(m, sw[l]);
        s_max = m;
    }
    __syncthreads();
    if (tid < 64) sw[tid] = expf(sw[tid] - s_max);
    __syncthreads();
    if (tid == 0) {
        float s = 0.f;
        for (int l = 0; l < 64; ++l) s += sw[l];
        s_inv = 1.f / s;
    }
    __syncthreads();
    if (tid < 64) sw[tid] *= s_inv;
    __syncthreads();
    const float* eb = g_enc + (long long)b * LMAX * DH;
    for (int d = tid; d < DH; d += 256) {
        float a = 0.f;
#pragma unroll 8
        for (int l = 0; l < 64; ++l) a += sw[l] * eb[(long long)l * DH + d];
        g_ctx[b * DH + d] = a;
    }
}

// ---------------- sum comb partials (bias already in slab 0) + relu ----------------
extern "C" __global__ void reduce_relu_kernel()
{
    int b = blockIdx.x, tid = threadIdx.x;
    for (int d = tid; d < DH; d += 256) {
        float v = 0.f;
#pragma unroll
        for (int p = 0; p < 8; ++p) v += g_combP[(long long)p * BB * DH + b * DH + d];
        g_inp[b * DH + d] = fmaxf(v, 0.f);
    }
}

// ---------------- in-place log_softmax + argmax (first-index tie break) ----------------
extern "C" __global__ void logsm_kernel(float* __restrict__ base, long long rowStride)
{
    __shared__ float rv[256];
    __shared__ int   ri[256];
    __shared__ float s_lse;
    int b = blockIdx.x, tid = threadIdx.x;
    float* row = base + (long long)b * rowStride;

    float bm = -3.4e38f; int bi = 0;
    for (int v = tid; v < NV; v += 256) {            // 32000/256 = 125 exact
        float z = row[v];
        if (z > bm) { bm = z; bi = v; }
    }
    rv[tid] = bm; ri[tid] = bi;
    __syncthreads();
    for (int off = 128; off > 0; off >>= 1) {
        if (tid < off) {
            float ov = rv[tid + off]; int oi = ri[tid + off];
            if (ov > rv[tid] || (ov == rv[tid] && oi < ri[tid])) { rv[tid] = ov; ri[tid] = oi; }
        }
        __syncthreads();
    }
    float mx = rv[0];
    int amx = ri[0];
    __syncthreads();

    float sm = 0.f;
    for (int v = tid; v < NV; v += 256) sm += expf(row[v] - mx);
    rv[tid] = sm;
    __syncthreads();
    for (int off = 128; off > 0; off >>= 1) {
        if (tid < off) rv[tid] += rv[tid + off];
        __syncthreads();
    }
    if (tid == 0) { s_lse = mx + logf(rv[0]); g_tok[b] = amx; }
    __syncthreads();
    float lse = s_lse;
    for (int v = tid; v < NV; v += 256) row[v] -= lse;
}

// ---------------- reset h,c (and tokens for decoder start) ----------------
extern "C" __global__ void reset_state(int setTok)
{
    int i = blockIdx.x * blockDim.x + threadIdx.x;
    if (i < BB * DH) { g_h[i] = 0.f; g_c[i] = 0.f; }
    if (setTok && i < BB) g_tok[i] = 127;
}

// ---------------------------------------------------------------------
extern "C" void kernel_launch(void* const* d_in, const int* in_sizes, int n_in,
                              void* d_out, int out_size)
{
    const int*   x         = (const int*)  d_in[0];
    const float* enc_embed = (const float*)d_in[1];
    const float* enc_wx    = (const float*)d_in[2];
    const float* enc_wh    = (const float*)d_in[3];
    const float* enc_b     = (const float*)d_in[4];
    const float* dec_embed = (const float*)d_in[5];
    const float* attn_w    = (const float*)d_in[6];
    const float* attn_b    = (const float*)d_in[7];
    const float* comb_w    = (const float*)d_in[8];
    const float* comb_b    = (const float*)d_in[9];
    const float* dec_wx    = (const float*)d_in[10];
    const float* dec_wh    = (const float*)d_in[11];
    const float* dec_b     = (const float*)d_in[12];
    const float* out_w     = (const float*)d_in[13];
    const float* out_b     = (const float*)d_in[14];
    float* out = (float*)d_out;

    cudaFuncSetAttribute(linear32, cudaFuncAttributeMaxDynamicSharedMemorySize, 1024 * 36 * 4);

    float *hB, *cB, *encB, *eB, *ctxB, *inpB, *combPB, *gatePB; int* tokB;
    cudaGetSymbolAddress((void**)&hB,     g_h);
    cudaGetSymbolAddress((void**)&cB,     g_c);
    cudaGetSymbolAddress((void**)&encB,   g_enc);
    cudaGetSymbolAddress((void**)&eB,     g_e);
    cudaGetSymbolAddress((void**)&ctxB,   g_ctx);
    cudaGetSymbolAddress((void**)&inpB,   g_inp);
    cudaGetSymbolAddress((void**)&combPB, g_combP);
    cudaGetSymbolAddress((void**)&gatePB, g_gateP);
    cudaGetSymbolAddress((void**)&tokB,   g_tok);

    (void)in_sizes; (void)n_in; (void)out_size;

    const int smemGate = 512  * 36 * 4;   // Kc max 512
    const int smemComb = 256  * 36 * 4;   // Kc 256
    const int smemProj = 1024 * 36 * 4;   // Kc 1024

    // ---------------- encoder ----------------
    reset_state<<<(BB * DH + 255) / 256, 256>>>(0);
    for (int t = 0; t < LMAX; ++t) {
        // gates partials: chunk0 = embed[x[:,t]] @ enc_wx (K=512), chunk1 = h @ enc_wh (K=1024)
        linear32<<<dim3(64, 2, 2), 128, smemGate>>>(
            enc_embed, EMB, x + t, LMAX, EMB, enc_wx,
            hB, DH, DH, enc_wh,
            G4, nullptr, gatePB, G4, (long long)BB * G4, 2);
        lstm_kernel<<<BB, 256>>>(gatePB, enc_b, encB + (long long)t * DH, 4);
    }

    // ---------------- decoder ----------------
    reset_state<<<(BB * DH + 255) / 256, 256>>>(1);
    for (int t = 0; t < LMAX; ++t) {
        attn_ctx<<<BB, 256>>>(dec_embed, attn_w, attn_b);

        // comb partials: chunk0 = e @ comb_w[0:1024], chunk1 = ctx @ comb_w[1024:2048]
        linear32<<<dim3(32, 4, 2), 64, smemComb>>>(
            eB, DH, nullptr, 0, DH, comb_w,
            ctxB, DH, DH, comb_w + (long long)DH * DH,
            DH, comb_b, combPB, DH, (long long)BB * DH, 4);
        reduce_relu_kernel<<<BB, 256>>>();

        // gate partials: chunk0 = inp @ dec_wx, chunk1 = h @ dec_wh
        linear32<<<dim3(64, 2, 2), 128, smemGate>>>(
            inpB, DH, nullptr, 0, DH, dec_wx,
            hB, DH, DH, dec_wh,
            G4, nullptr, gatePB, G4, (long long)BB * G4, 2);
        lstm_kernel<<<BB, 256>>>(gatePB, dec_b, nullptr, 4);

        // output projection with NEW h: logits -> d_out[b][t][:]
        linear32<<<dim3(250, 1, 1), 256, smemProj>>>(
            hB, DH, nullptr, 0, DH, out_w,
            hB, DH, DH, out_w,                    // chunk1 unused (gridDim.z == 1)
            NV, out_b, out + (long long)t * NV, (long long)LMAX * NV, 0, 1);

        logsm_kernel<<<BB, 256>>>(out + (long long)t * NV, (long long)LMAX * NV);
    }
}

// round 9
// speedup vs baseline: 2.2419x; 2.2419x over previous
#include <cuda_runtime.h>

#define BB    32
#define LMAX  64
#define EMB   512
#define DH    1024
#define G4    4096
#define NV    32000

#define PROJ_SPLIT 4
#define NLCH   16            // log-softmax chunks per row
#define LCHUNK (NV / NLCH)   // 2000

// ---------------- device state (no allocation allowed) ----------------
__device__ float g_h[BB * DH];
__device__ float g_c[BB * DH];
__device__ float g_enc[BB * LMAX * DH];        // [b][l][d]
__device__ float g_e[BB * DH];                 // decoder embedding of current token
__device__ float g_ctx[BB * DH];               // attention context
__device__ float g_inp[BB * DH];               // relu(comb) = LSTM x-input
__device__ float g_combP[16 * BB * DH];        // comb partial slabs (2 chunks x kSplit 8)
__device__ float g_gateP[8 * BB * G4];         // gate partial slabs (2 chunks x kSplit 4)
__device__ float g_projP[PROJ_SPLIT * BB * NV];// projection partial slabs
__device__ float g_pm[BB * NLCH];              // per-chunk max
__device__ int   g_pi[BB * NLCH];              // per-chunk argmax (global v index)
__device__ float g_ps[BB * NLCH];              // per-chunk sum exp(z - chunk max)
__device__ float g_lse[BB];
__device__ int   g_tok[BB];

// ---------------- f32x2 packed-FMA helpers ----------------
__device__ __forceinline__ unsigned long long pk2(float x, float y) {
    unsigned long long r;
    asm("mov.b64 %0, {%1, %2};" : "=l"(r) : "r"(__float_as_uint(x)), "r"(__float_as_uint(y)));
    return r;
}
__device__ __forceinline__ void upk2(unsigned long long v, float& lo, float& hi) {
    unsigned a, b;
    asm("mov.b64 {%0, %1}, %2;" : "=r"(a), "=r"(b) : "l"(v));
    lo = __uint_as_float(a); hi = __uint_as_float(b);
}
__device__ __forceinline__ unsigned long long ff2(unsigned long long a, unsigned long long b,
                                                  unsigned long long c) {
    unsigned long long d;
    asm("fma.rn.f32x2 %0, %1, %2, %3;" : "=l"(d) : "l"(a), "l"(b), "l"(c));
    return d;
}

// ---------------------------------------------------------------------
// Skinny GEMM: OUT[b][j] = sum_k IN[b][k] * W[k][j]  (32 rows)
// - JC = columns per thread (2 or 4); block = 256 threads:
//     64 threads span j, 4 groups of 8 batch rows each
// - gridDim.z selects chunk; gridDim.y = kSplit -> deterministic partial slabs
// - input staged transposed in smem (stride 36, 16B-aligned batch pairs)
// - f32x2 accumulators over batch pairs; weight loads LDG.128 (JC=4) / LDG.64
// - optional token-gather rows for chunk 0; bias added only in slab 0
// ---------------------------------------------------------------------
template<int JC>
__global__ void __launch_bounds__(256)
linearT(const float* __restrict__ in0, long long in0Stride,
        const int* __restrict__ tok0, int tok0Stride, int K0,
        const float* __restrict__ W0,
        const float* __restrict__ in1, long long in1Stride, int K1,
        const float* __restrict__ W1,
        int N, const float* __restrict__ bias,
        float* __restrict__ out, long long outRowStride,
        long long outSlabStride, int kSplit)
{
    extern __shared__ float s_in[];

    const float* in; const float* W; const int* tok = nullptr;
    int tokStride = 0; long long inStride; int K;
    if (blockIdx.z == 0) { in = in0; W = W0; tok = tok0; tokStride = tok0Stride; inStride = in0Stride; K = K0; }
    else                 { in = in1; W = W1;                                     inStride = in1Stride; K = K1; }

    const int Kc  = K / kSplit;
    const int k0  = blockIdx.y * Kc;
    const int tid = threadIdx.x;

    // stage input slice transposed: s_in[k*36 + b] (coalesced global reads)
    for (int idx = tid; idx < BB * Kc; idx += 256) {
        int b = idx / Kc;
        int k = idx - b * Kc;
        long long row = tok ? (long long)tok[b * tokStride] * inStride
                            : (long long)b * inStride;
        s_in[(unsigned)k * 36u + b] = in[row + k0 + k];
    }
    __syncthreads();

    const int tj = tid & 63;
    const int bg = tid >> 6;
    const int b0 = bg * 8;
    const int jA = blockIdx.x * (64 * JC) + tj * JC;

    const float* Wp = W + (long long)k0 * N + jA;
    const float* sp = s_in + b0;

    unsigned long long acc[JC][4];
#pragma unroll
    for (int j = 0; j < JC; ++j)
#pragma unroll
        for (int r = 0; r < 4; ++r) acc[j][r] = 0ull;

#pragma unroll 4
    for (int k = 0; k < Kc; ++k) {
        float wv[JC];
        if (JC == 4) {
            float4 w = *reinterpret_cast<const float4*>(Wp);
            wv[0] = w.x; wv[1] = w.y; wv[2] = w.z; wv[3] = w.w;
        } else {
            float2 w = *reinterpret_cast<const float2*>(Wp);
            wv[0] = w.x; wv[1] = w.y;
        }
        Wp += N;
        unsigned long long wp2[JC];
#pragma unroll
        for (int j = 0; j < JC; ++j) wp2[j] = pk2(wv[j], wv[j]);

        const ulonglong2* sr = reinterpret_cast<const ulonglong2*>(sp);
        ulonglong2 p0 = sr[0];   // batch rows b0..b0+3
        ulonglong2 p1 = sr[1];   // batch rows b0+4..b0+7
#pragma unroll
        for (int j = 0; j < JC; ++j) {
            acc[j][0] = ff2(p0.x, wp2[j], acc[j][0]);
            acc[j][1] = ff2(p0.y, wp2[j], acc[j][1]);
            acc[j][2] = ff2(p1.x, wp2[j], acc[j][2]);
            acc[j][3] = ff2(p1.y, wp2[j], acc[j][3]);
        }
        sp += 36;
    }

    const int si = blockIdx.z * kSplit + blockIdx.y;
    float bj[JC];
#pragma unroll
    for (int j = 0; j < JC; ++j) bj[j] = (si == 0 && bias) ? bias[jA + j] : 0.f;

    float* ob = out + (long long)si * outSlabStride;

#pragma unroll
    for (int r = 0; r < 4; ++r) {
        float lo[JC], hi[JC];
#pragma unroll
        for (int j = 0; j < JC; ++j) upk2(acc[j][r], lo[j], hi[j]);
        float* r0 = ob + (long long)(b0 + 2 * r) * outRowStride + jA;
        float* r1 = r0 + outRowStride;
        if (JC == 4) {
            *reinterpret_cast<float4*>(r0) =
                make_float4(lo[0] + bj[0], lo[1] + bj[1], lo[2] + bj[2], lo[3] + bj[3]);
            *reinterpret_cast<float4*>(r1) =
                make_float4(hi[0] + bj[0], hi[1] + bj[1], hi[2] + bj[2], hi[3] + bj[3]);
        } else {
            *reinterpret_cast<float2*>(r0) = make_float2(lo[0] + bj[0], lo[1] + bj[1]);
            *reinterpret_cast<float2*>(r1) = make_float2(hi[0] + bj[0], hi[1] + bj[1]);
        }
    }
}

// ---------------- LSTM pointwise: sum gate partials + bias, update h,c ----------------
extern "C" __global__ void lstm_kernel(const float* __restrict__ P,
                                       const float* __restrict__ bias,
                                       float* __restrict__ encOut, int nParts)
{
    int b = blockIdx.x;
    int d = blockIdx.y * 256 + threadIdx.x;
    float gi = bias[d], gf = bias[DH + d], gg = bias[2 * DH + d], go = bias[3 * DH + d];
    for (int p = 0; p < nParts; ++p) {
        const float* pb = P + (long long)p * BB * G4 + (long long)b * G4;
        gi += pb[d]; gf += pb[DH + d]; gg += pb[2 * DH + d]; go += pb[3 * DH + d];
    }
    float iv = 1.f / (1.f + expf(-gi));
    float fv = 1.f / (1.f + expf(-gf));
    float gv = tanhf(gg);
    float ov = 1.f / (1.f + expf(-go));
    float cv = fv * g_c[b * DH + d] + iv * gv;
    float hv = ov * tanhf(cv);
    g_c[b * DH + d] = cv;
    g_h[b * DH + d] = hv;
    if (encOut) encOut[(long long)b * LMAX * DH + d] = hv;
}

// ---------------- decoder: embed gather + attention softmax + context ----------------
extern "C" __global__ void attn_ctx(const float* __restrict__ dec_embed,
                                    const float* __restrict__ attn_w,
                                    const float* __restrict__ attn_b)
{
    __shared__ float se[DH], sh[DH], sp[4 * 64], sw[64];
    __shared__ float s_max, s_inv;
    int b = blockIdx.x, tid = threadIdx.x;
    int tk = g_tok[b];
    for (int d = tid; d < DH; d += 256) {
        float ev = dec_embed[(long long)tk * DH + d];
        se[d] = ev;
        g_e[b * DH + d] = ev;
        sh[d] = g_h[b * DH + d];
    }
    __syncthreads();
    {
        int l = tid & 63, q = tid >> 6;                    // 4 k-quarters of 512
        const float* src = (q < 2) ? (se + q * 512) : (sh + (q - 2) * 512);
        const float* wp  = attn_w + (long long)(q * 512) * 64 + l;
        float a = 0.f;
#pragma unroll 8
        for (int kk = 0; kk < 512; ++kk) a += src[kk] * wp[(long long)kk * 64];
        sp[q * 64 + l] = a;
    }
    __syncthreads();
    if (tid < 64)
        sw[tid] = sp[tid] + sp[64 + tid] + sp[128 + tid] + sp[192 + tid] + attn_b[tid];
    __syncthreads();
    if (tid == 0) {
        float m = sw[0];
        for (int l = 1; l < 64; ++l) m = fmaxf(m, sw[l]);
        s_max = m;
    }
    __syncthreads();
    if (tid < 64) sw[tid] = expf(sw[tid] - s_max);
    __syncthreads();
    if (tid == 0) {
        float s = 0.f;
        for (int l = 0; l < 64; ++l) s += sw[l];
        s_inv = 1.f / s;
    }
    __syncthreads();
    if (tid < 64) sw[tid] *= s_inv;
    __syncthreads();
    const float* eb = g_enc + (long long)b * LMAX * DH;
    for (int d = tid; d < DH; d += 256) {
        float a = 0.f;
#pragma unroll 8
        for (int l = 0; l < 64; ++l) a += sw[l] * eb[(long long)l * DH + d];
        g_ctx[b * DH + d] = a;
    }
}

// ---------------- sum comb partials (bias already in slab 0) + relu ----------------
extern "C" __global__ void reduce_relu_kernel()
{
    int b = blockIdx.x;
    int d = blockIdx.y * 256 + threadIdx.x;
    float v = 0.f;
#pragma unroll
    for (int p = 0; p < 16; ++p) v += g_combP[(long long)p * BB * DH + b * DH + d];
    g_inp[b * DH + d] = fmaxf(v, 0.f);
}

// ---------------- log-softmax phase 1: slab-reduce + chunk max/argmax/expsum ----------------
extern "C" __global__ void __launch_bounds__(256)
logsm_phase1(const float* __restrict__ bias, float* __restrict__ out, long long rowStride)
{
    __shared__ float sz[LCHUNK];     // combined logits for this chunk
    __shared__ float rm[256];
    __shared__ int   rix[256];
    __shared__ float rs[256];
    int b = blockIdx.x, c = blockIdx.y, tid = threadIdx.x;
    int v0 = c * LCHUNK;
    float* row = out + (long long)b * rowStride;

    float m = -3.4e38f; int mi = 0;
    for (int v = tid; v < LCHUNK; v += 256) {
        int gv = v0 + v;
        float z = bias[gv];
#pragma unroll
        for (int s = 0; s < PROJ_SPLIT; ++s)
            z += g_projP[(long long)s * BB * NV + (long long)b * NV + gv];
        sz[v] = z;
        row[gv] = z;
        if (z > m) { m = z; mi = gv; }
    }
    rm[tid] = m; rix[tid] = mi;
    __syncthreads();
    for (int off = 128; off > 0; off >>= 1) {
        if (tid < off) {
            float ov = rm[tid + off]; int oi = rix[tid + off];
            if (ov > rm[tid] || (ov == rm[tid] && oi < rix[tid])) { rm[tid] = ov; rix[tid] = oi; }
        }
        __syncthreads();
    }
    float mb = rm[0]; int ib = rix[0];
    __syncthreads();

    float s = 0.f;
    for (int v = tid; v < LCHUNK; v += 256) s += expf(sz[v] - mb);
    rs[tid] = s;
    __syncthreads();
    for (int off = 128; off > 0; off >>= 1) {
        if (tid < off) rs[tid] += rs[tid + off];
        __syncthreads();
    }
    if (tid == 0) {
        g_pm[b * NLCH + c] = mb;
        g_pi[b * NLCH + c] = ib;
        g_ps[b * NLCH + c] = rs[0];
    }
}

// ---------------- log-softmax phase 2: combine chunks -> lse, argmax token ----------------
extern "C" __global__ void logsm_phase2()
{
    int b = threadIdx.x;
    if (b < BB) {
        float M = -3.4e38f;
        for (int c = 0; c < NLCH; ++c) M = fmaxf(M, g_pm[b * NLCH + c]);
        float s = 0.f; int idx = 0; bool found = false;
        for (int c = 0; c < NLCH; ++c) {
            s += g_ps[b * NLCH + c] * expf(g_pm[b * NLCH + c] - M);
            if (!found && g_pm[b * NLCH + c] == M) { idx = g_pi[b * NLCH + c]; found = true; }
        }
        g_lse[b] = M + logf(s);
        g_tok[b] = idx;
    }
}

// ---------------- log-softmax phase 3: subtract lse ----------------
extern "C" __global__ void __launch_bounds__(256)
logsm_phase3(float* __restrict__ out, long long rowStride)
{
    int b = blockIdx.x, c = blockIdx.y, tid = threadIdx.x;
    float lse = g_lse[b];
    float* row = out + (long long)b * rowStride + (long long)c * LCHUNK;
    for (int v = tid; v < LCHUNK; v += 256) row[v] -= lse;
}

// ---------------- reset h,c (and tokens for decoder start) ----------------
extern "C" __global__ void reset_state(int setTok)
{
    int i = blockIdx.x * blockDim.x + threadIdx.x;
    if (i < BB * DH) { g_h[i] = 0.f; g_c[i] = 0.f; }
    if (setTok && i < BB) g_tok[i] = 127;
}

// ---------------------------------------------------------------------
extern "C" void kernel_launch(void* const* d_in, const int* in_sizes, int n_in,
                              void* d_out, int out_size)
{
    const int*   x         = (const int*)  d_in[0];
    const float* enc_embed = (const float*)d_in[1];
    const float* enc_wx    = (const float*)d_in[2];
    const float* enc_wh    = (const float*)d_in[3];
    const float* enc_b     = (const float*)d_in[4];
    const float* dec_embed = (const float*)d_in[5];
    const float* attn_w    = (const float*)d_in[6];
    const float* attn_b    = (const float*)d_in[7];
    const float* comb_w    = (const float*)d_in[8];
    const float* comb_b    = (const float*)d_in[9];
    const float* dec_wx    = (const float*)d_in[10];
    const float* dec_wh    = (const float*)d_in[11];
    const float* dec_b     = (const float*)d_in[12];
    const float* out_w     = (const float*)d_in[13];
    const float* out_b     = (const float*)d_in[14];
    float* out = (float*)d_out;

    float *hB, *encB, *eB, *ctxB, *inpB, *combPB, *gatePB, *projPB;
    cudaGetSymbolAddress((void**)&hB,     g_h);
    cudaGetSymbolAddress((void**)&encB,   g_enc);
    cudaGetSymbolAddress((void**)&eB,     g_e);
    cudaGetSymbolAddress((void**)&ctxB,   g_ctx);
    cudaGetSymbolAddress((void**)&inpB,   g_inp);
    cudaGetSymbolAddress((void**)&combPB, g_combP);
    cudaGetSymbolAddress((void**)&gatePB, g_gateP);
    cudaGetSymbolAddress((void**)&projPB, g_projP);

    (void)in_sizes; (void)n_in; (void)out_size;

    const int smemGate = 256 * 36 * 4;   // max Kc 256
    const int smemComb = 128 * 36 * 4;   // Kc 128
    const int smemProj = 256 * 36 * 4;   // Kc 256

    // ---------------- encoder ----------------
    reset_state<<<(BB * DH + 255) / 256, 256>>>(0);
    for (int t = 0; t < LMAX; ++t) {
        // gates: chunk0 = embed[x[:,t]] @ enc_wx (K=512), chunk1 = h @ enc_wh (K=1024)
        linearT<2><<<dim3(32, 4, 2), 256, smemGate>>>(
            enc_embed, EMB, x + t, LMAX, EMB, enc_wx,
            hB, DH, DH, enc_wh,
            G4, nullptr, gatePB, G4, (long long)BB * G4, 4);
        lstm_kernel<<<dim3(BB, 4), 256>>>(gatePB, enc_b, encB + (long long)t * DH, 8);
    }

    // ---------------- decoder ----------------
    reset_state<<<(BB * DH + 255) / 256, 256>>>(1);
    for (int t = 0; t < LMAX; ++t) {
        attn_ctx<<<BB, 256>>>(dec_embed, attn_w, attn_b);

        // comb: chunk0 = e @ comb_w[0:1024], chunk1 = ctx @ comb_w[1024:2048]
        linearT<2><<<dim3(8, 8, 2), 256, smemComb>>>(
            eB, DH, nullptr, 0, DH, comb_w,
            ctxB, DH, DH, comb_w + (long long)DH * DH,
            DH, comb_b, combPB, DH, (long long)BB * DH, 8);
        reduce_relu_kernel<<<dim3(BB, 4), 256>>>();

        // gates: chunk0 = inp @ dec_wx, chunk1 = h @ dec_wh
        linearT<2><<<dim3(32, 4, 2), 256, smemGate>>>(
            inpB, DH, nullptr, 0, DH, dec_wx,
            hB, DH, DH, dec_wh,
            G4, nullptr, gatePB, G4, (long long)BB * G4, 4);
        lstm_kernel<<<dim3(BB, 4), 256>>>(gatePB, dec_b, nullptr, 8);

        // output projection with NEW h -> 4 partial slabs
        linearT<4><<<dim3(125, PROJ_SPLIT, 1), 256, smemProj>>>(
            hB, DH, nullptr, 0, DH, out_w,
            hB, DH, DH, out_w,                // chunk1 unused (gridDim.z == 1)
            NV, nullptr, projPB, NV, (long long)BB * NV, PROJ_SPLIT);

        // log-softmax: reduce slabs + bias, max/argmax, lse, subtract
        logsm_phase1<<<dim3(BB, NLCH), 256>>>(out_b, out + (long long)t * NV,
                                              (long long)LMAX * NV);
        logsm_phase2<<<1, 32>>>();
        logsm_phase3<<<dim3(BB, NLCH), 256>>>(out + (long long)t * NV,
                                              (long long)LMAX * NV);
    }
}

// round 10
// speedup vs baseline: 2.6617x; 1.1873x over previous
#include <cuda_runtime.h>

#define BB    32
#define LMAX  64
#define EMB   512
#define DH    1024
#define G4    4096
#define NV    32000

#define PROJ_SPLIT 4
#define NLCH   16            // log-softmax chunks per row
#define LCHUNK (NV / NLCH)   // 2000

// ---------------- device state (no allocation allowed) ----------------
__device__ float g_h[BB * DH];
__device__ float g_c[BB * DH];
__device__ float g_enc[BB * LMAX * DH];        // [b][l][d]
__device__ float g_e[BB * DH];                 // decoder embedding of current token
__device__ float g_ctx[BB * DH];               // attention context
__device__ float g_inp[BB * DH];               // relu(comb) = LSTM x-input
__device__ float g_combP[16 * BB * DH];        // comb partial slabs (2 x 8)
__device__ float g_gateP[16 * BB * G4];        // gate partial slabs (up to 16)
__device__ float g_projP[PROJ_SPLIT * BB * NV];// projection partial slabs
__device__ float g_pm[BB * NLCH];              // per-chunk max
__device__ int   g_pi[BB * NLCH];              // per-chunk argmax (global v index)
__device__ float g_ps[BB * NLCH];              // per-chunk sum exp(z - chunk max)
__device__ float g_lseAll[LMAX * BB];          // lse per (t, b) for deferred subtract
__device__ unsigned g_cnt[BB];                 // phase1 completion counters (self-reset)
__device__ int   g_tok[BB];

// ---------------- f32x2 packed-FMA helpers ----------------
__device__ __forceinline__ unsigned long long pk2(float x, float y) {
    unsigned long long r;
    asm("mov.b64 %0, {%1, %2};" : "=l"(r) : "r"(__float_as_uint(x)), "r"(__float_as_uint(y)));
    return r;
}
__device__ __forceinline__ void upk2(unsigned long long v, float& lo, float& hi) {
    unsigned a, b;
    asm("mov.b64 {%0, %1}, %2;" : "=r"(a), "=r"(b) : "l"(v));
    lo = __uint_as_float(a); hi = __uint_as_float(b);
}
__device__ __forceinline__ unsigned long long ff2(unsigned long long a, unsigned long long b,
                                                  unsigned long long c) {
    unsigned long long d;
    asm("fma.rn.f32x2 %0, %1, %2, %3;" : "=l"(d) : "l"(a), "l"(b), "l"(c));
    return d;
}

// ---------------------------------------------------------------------
// Skinny GEMM: OUT[b][j] = sum_k IN[b][k] * W[k][j]  (32 batch rows)
// - JC columns/thread (2 or 4), U = weight-load batch (MLP), 256 threads:
//     64 threads span j, 4 groups of 8 batch rows
// - blockIdx.y flat-indexes slabs of BOTH chunks: [0,split0) chunk0,
//   [split0, gridDim.y) chunk1; each slab writes a deterministic partial
// - input staged transposed in smem (stride 36, 16B-aligned batch pairs)
// - f32x2 accumulators over batch pairs; bias added only in slab 0
// - optional token-gather rows for chunk 0 (embedding lookup)
// ---------------------------------------------------------------------
template<int JC, int U>
__global__ void __launch_bounds__(256)
linearT(const float* __restrict__ in0, long long in0Stride,
        const int* __restrict__ tok0, int tok0Stride, int K0,
        const float* __restrict__ W0, int split0,
        const float* __restrict__ in1, long long in1Stride, int K1,
        const float* __restrict__ W1,
        int N, const float* __restrict__ bias,
        float* __restrict__ out, long long outRowStride,
        long long outSlabStride)
{
    extern __shared__ float s_in[];

    const int slab = blockIdx.y;
    const float* in; const float* W; const int* tok = nullptr;
    int tokStride = 0; long long inStride; int Kc, k0;
    if (slab < split0) {
        in = in0; W = W0; tok = tok0; tokStride = tok0Stride; inStride = in0Stride;
        Kc = K0 / split0; k0 = slab * Kc;
    } else {
        in = in1; W = W1; inStride = in1Stride;
        int split1 = gridDim.y - split0;
        Kc = K1 / split1; k0 = (slab - split0) * Kc;
    }

    const int tid = threadIdx.x;

    // stage input slice transposed: s_in[k*36 + b]
    for (int idx = tid; idx < BB * Kc; idx += 256) {
        int b = idx / Kc;
        int k = idx - b * Kc;
        long long row = tok ? (long long)tok[b * tokStride] * inStride
                            : (long long)b * inStride;
        s_in[(unsigned)k * 36u + b] = in[row + k0 + k];
    }
    __syncthreads();

    const int tj = tid & 63;
    const int bg = tid >> 6;
    const int b0 = bg * 8;
    const int jA = blockIdx.x * (64 * JC) + tj * JC;

    const float* Wp = W + (long long)k0 * N + jA;
    const float* sp = s_in + b0;

    unsigned long long acc[JC][4];
#pragma unroll
    for (int j = 0; j < JC; ++j)
#pragma unroll
        for (int r = 0; r < 4; ++r) acc[j][r] = 0ull;

    for (int kb = 0; kb < Kc; kb += U) {
        // batch-load U weight rows (front-batched LDGs -> MLP = U)
        float wv[U][JC];
#pragma unroll
        for (int u = 0; u < U; ++u) {
            if (JC == 4) {
                float4 w = *reinterpret_cast<const float4*>(Wp + (long long)u * N);
                wv[u][0] = w.x; wv[u][1] = w.y; wv[u][2] = w.z; wv[u][3] = w.w;
            } else {
                float2 w = *reinterpret_cast<const float2*>(Wp + (long long)u * N);
                wv[u][0] = w.x; wv[u][1] = w.y;
            }
        }
        Wp += (long long)U * N;

#pragma unroll
        for (int u = 0; u < U; ++u) {
            unsigned long long wp2[JC];
#pragma unroll
            for (int j = 0; j < JC; ++j) wp2[j] = pk2(wv[u][j], wv[u][j]);
            const ulonglong2* sr = reinterpret_cast<const ulonglong2*>(sp + u * 36);
            ulonglong2 p0 = sr[0];   // batch rows b0..b0+3
            ulonglong2 p1 = sr[1];   // batch rows b0+4..b0+7
#pragma unroll
            for (int j = 0; j < JC; ++j) {
                acc[j][0] = ff2(p0.x, wp2[j], acc[j][0]);
                acc[j][1] = ff2(p0.y, wp2[j], acc[j][1]);
                acc[j][2] = ff2(p1.x, wp2[j], acc[j][2]);
                acc[j][3] = ff2(p1.y, wp2[j], acc[j][3]);
            }
        }
        sp += U * 36;
    }

    float bj[JC];
#pragma unroll
    for (int j = 0; j < JC; ++j) bj[j] = (slab == 0 && bias) ? bias[jA + j] : 0.f;

    float* ob = out + (long long)slab * outSlabStride;

#pragma unroll
    for (int r = 0; r < 4; ++r) {
        float lo[JC], hi[JC];
#pragma unroll
        for (int j = 0; j < JC; ++j) upk2(acc[j][r], lo[j], hi[j]);
        float* r0 = ob + (long long)(b0 + 2 * r) * outRowStride + jA;
        float* r1 = r0 + outRowStride;
        if (JC == 4) {
            *reinterpret_cast<float4*>(r0) =
                make_float4(lo[0] + bj[0], lo[1] + bj[1], lo[2] + bj[2], lo[3] + bj[3]);
            *reinterpret_cast<float4*>(r1) =
                make_float4(hi[0] + bj[0], hi[1] + bj[1], hi[2] + bj[2], hi[3] + bj[3]);
        } else {
            *reinterpret_cast<float2*>(r0) = make_float2(lo[0] + bj[0], lo[1] + bj[1]);
            *reinterpret_cast<float2*>(r1) = make_float2(hi[0] + bj[0], hi[1] + bj[1]);
        }
    }
}

// ---------------- LSTM pointwise: sum gate partials + bias, update h,c ----------------
extern "C" __global__ void lstm_kernel(const float* __restrict__ P,
                                       const float* __restrict__ bias,
                                       float* __restrict__ encOut, int nParts)
{
    int b = blockIdx.x;
    int d = blockIdx.y * 256 + threadIdx.x;
    float gi = bias[d], gf = bias[DH + d], gg = bias[2 * DH + d], go = bias[3 * DH + d];
    for (int p = 0; p < nParts; ++p) {
        const float* pb = P + (long long)p * BB * G4 + (long long)b * G4;
        gi += pb[d]; gf += pb[DH + d]; gg += pb[2 * DH + d]; go += pb[3 * DH + d];
    }
    float iv = 1.f / (1.f + expf(-gi));
    float fv = 1.f / (1.f + expf(-gf));
    float gv = tanhf(gg);
    float ov = 1.f / (1.f + expf(-go));
    float cv = fv * g_c[b * DH + d] + iv * gv;
    float hv = ov * tanhf(cv);
    g_c[b * DH + d] = cv;
    g_h[b * DH + d] = hv;
    if (encOut) encOut[(long long)b * LMAX * DH + d] = hv;
}

// ---------------- decoder: embed gather + attention softmax + context ----------------
extern "C" __global__ void attn_ctx(const float* __restrict__ dec_embed,
                                    const float* __restrict__ attn_w,
                                    const float* __restrict__ attn_b)
{
    __shared__ float se[DH], sh[DH], sp[4 * 64], sw[64];
    __shared__ float s_max, s_inv;
    int b = blockIdx.x, tid = threadIdx.x;
    int tk = g_tok[b];
    for (int d = tid; d < DH; d += 256) {
        float ev = dec_embed[(long long)tk * DH + d];
        se[d] = ev;
        g_e[b * DH + d] = ev;
        sh[d] = g_h[b * DH + d];
    }
    __syncthreads();
    {
        int l = tid & 63, q = tid >> 6;                    // 4 k-quarters of 512
        const float* src = (q < 2) ? (se + q * 512) : (sh + (q - 2) * 512);
        const float* wp  = attn_w + (long long)(q * 512) * 64 + l;
        float a = 0.f;
#pragma unroll 8
        for (int kk = 0; kk < 512; ++kk) a += src[kk] * wp[(long long)kk * 64];
        sp[q * 64 + l] = a;
    }
    __syncthreads();
    if (tid < 64)
        sw[tid] = sp[tid] + sp[64 + tid] + sp[128 + tid] + sp[192 + tid] + attn_b[tid];
    __syncthreads();
    if (tid == 0) {
        float m = sw[0];
        for (int l = 1; l < 64; ++l) m = fmaxf(m, sw[l]);
        s_max = m;
    }
    __syncthreads();
    if (tid < 64) sw[tid] = expf(sw[tid] - s_max);
    __syncthreads();
    if (tid == 0) {
        float s = 0.f;
        for (int l = 0; l < 64; ++l) s += sw[l];
        s_inv = 1.f / s;
    }
    __syncthreads();
    if (tid < 64) sw[tid] *= s_inv;
    __syncthreads();
    const float* eb = g_enc + (long long)b * LMAX * DH;
    for (int d = tid; d < DH; d += 256) {
        float a = 0.f;
#pragma unroll 8
        for (int l = 0; l < 64; ++l) a += sw[l] * eb[(long long)l * DH + d];
        g_ctx[b * DH + d] = a;
    }
}

// ---------------- sum comb partials (bias already in slab 0) + relu ----------------
extern "C" __global__ void reduce_relu_kernel()
{
    int b = blockIdx.x;
    int d = blockIdx.y * 256 + threadIdx.x;
    float v = 0.f;
#pragma unroll
    for (int p = 0; p < 16; ++p) v += g_combP[(long long)p * BB * DH + b * DH + d];
    g_inp[b * DH + d] = fmaxf(v, 0.f);
}

// ---------------- log-softmax phase 1: slab-reduce + chunk stats + last-block combine ----
// Writes raw logits z to out; last block per batch row combines chunk stats into
// lse (stored for deferred subtraction) and argmax token. Deterministic: combine
// result is independent of block arrival order.
extern "C" __global__ void __launch_bounds__(256)
logsm_phase1(const float* __restrict__ bias, float* __restrict__ out,
             long long rowStride, float* __restrict__ lse_t)
{
    __shared__ float sz[LCHUNK];
    __shared__ float rm[256];
    __shared__ int   rix[256];
    __shared__ float rs[256];
    __shared__ int   sIsLast;
    int b = blockIdx.x, c = blockIdx.y, tid = threadIdx.x;
    int v0 = c * LCHUNK;
    float* row = out + (long long)b * rowStride;

    float m = -3.4e38f; int mi = 0;
    for (int v = tid; v < LCHUNK; v += 256) {
        int gv = v0 + v;
        float z = bias[gv];
#pragma unroll
        for (int s = 0; s < PROJ_SPLIT; ++s)
            z += g_projP[(long long)s * BB * NV + (long long)b * NV + gv];
        sz[v] = z;
        row[gv] = z;
        if (z > m) { m = z; mi = gv; }
    }
    rm[tid] = m; rix[tid] = mi;
    __syncthreads();
    for (int off = 128; off > 0; off >>= 1) {
        if (tid < off) {
            float ov = rm[tid + off]; int oi = rix[tid + off];
            if (ov > rm[tid] || (ov == rm[tid] && oi < rix[tid])) { rm[tid] = ov; rix[tid] = oi; }
        }
        __syncthreads();
    }
    float mb = rm[0]; int ib = rix[0];
    __syncthreads();

    float s = 0.f;
    for (int v = tid; v < LCHUNK; v += 256) s += expf(sz[v] - mb);
    rs[tid] = s;
    __syncthreads();
    for (int off = 128; off > 0; off >>= 1) {
        if (tid < off) rs[tid] += rs[tid + off];
        __syncthreads();
    }
    if (tid == 0) {
        g_pm[b * NLCH + c] = mb;
        g_pi[b * NLCH + c] = ib;
        g_ps[b * NLCH + c] = rs[0];
        __threadfence();
        unsigned prev = atomicAdd(&g_cnt[b], 1u);
        sIsLast = (prev == NLCH - 1);
    }
    __syncthreads();
    if (sIsLast && tid == 0) {
        __threadfence();
        float M = -3.4e38f;
        for (int k = 0; k < NLCH; ++k) M = fmaxf(M, g_pm[b * NLCH + k]);
        float S = 0.f; int idx = 0; bool found = false;
        for (int k = 0; k < NLCH; ++k) {
            S += g_ps[b * NLCH + k] * expf(g_pm[b * NLCH + k] - M);
            if (!found && g_pm[b * NLCH + k] == M) { idx = g_pi[b * NLCH + k]; found = true; }
        }
        lse_t[b] = M + logf(S);
        g_tok[b] = idx;
        g_cnt[b] = 0;              // self-reset for next step / next replay
    }
}

// ---------------- deferred: subtract lse from every output row ----------------
extern "C" __global__ void __launch_bounds__(256)
sub_lse_kernel(float* __restrict__ out)
{
    int b = blockIdx.x, t = blockIdx.y, tid = threadIdx.x;
    float lse = g_lseAll[t * BB + b];
    float* row = out + ((long long)b * LMAX + t) * NV;
    for (int v = tid; v < NV; v += 256) row[v] -= lse;
}

// ---------------- reset h,c (and tokens for decoder start) ----------------
extern "C" __global__ void reset_state(int setTok)
{
    int i = blockIdx.x * blockDim.x + threadIdx.x;
    if (i < BB * DH) { g_h[i] = 0.f; g_c[i] = 0.f; }
    if (setTok && i < BB) g_tok[i] = 127;
    if (i < BB) g_cnt[i] = 0;
}

// ---------------------------------------------------------------------
extern "C" void kernel_launch(void* const* d_in, const int* in_sizes, int n_in,
                              void* d_out, int out_size)
{
    const int*   x         = (const int*)  d_in[0];
    const float* enc_embed = (const float*)d_in[1];
    const float* enc_wx    = (const float*)d_in[2];
    const float* enc_wh    = (const float*)d_in[3];
    const float* enc_b     = (const float*)d_in[4];
    const float* dec_embed = (const float*)d_in[5];
    const float* attn_w    = (const float*)d_in[6];
    const float* attn_b    = (const float*)d_in[7];
    const float* comb_w    = (const float*)d_in[8];
    const float* comb_b    = (const float*)d_in[9];
    const float* dec_wx    = (const float*)d_in[10];
    const float* dec_wh    = (const float*)d_in[11];
    const float* dec_b     = (const float*)d_in[12];
    const float* out_w     = (const float*)d_in[13];
    const float* out_b     = (const float*)d_in[14];
    float* out = (float*)d_out;

    float *hB, *encB, *eB, *ctxB, *inpB, *combPB, *gatePB, *projPB, *lseB;
    cudaGetSymbolAddress((void**)&hB,     g_h);
    cudaGetSymbolAddress((void**)&encB,   g_enc);
    cudaGetSymbolAddress((void**)&eB,     g_e);
    cudaGetSymbolAddress((void**)&ctxB,   g_ctx);
    cudaGetSymbolAddress((void**)&inpB,   g_inp);
    cudaGetSymbolAddress((void**)&combPB, g_combP);
    cudaGetSymbolAddress((void**)&gatePB, g_gateP);
    cudaGetSymbolAddress((void**)&projPB, g_projP);
    cudaGetSymbolAddress((void**)&lseB,   g_lseAll);

    (void)in_sizes; (void)n_in; (void)out_size;

    const int smem128 = 128 * 36 * 4;   // Kc = 128 (gates, comb)
    const int smem256 = 256 * 36 * 4;   // Kc = 256 (projection)

    // ---------------- encoder ----------------
    reset_state<<<(BB * DH + 255) / 256, 256>>>(0);
    for (int t = 0; t < LMAX; ++t) {
        // gates: chunk0 = embed[x[:,t]] @ enc_wx (K=512, split 4),
        //        chunk1 = h @ enc_wh            (K=1024, split 8)  -> 12 slabs
        linearT<2, 8><<<dim3(32, 12), 256, smem128>>>(
            enc_embed, EMB, x + t, LMAX, EMB, enc_wx, 4,
            hB, DH, DH, enc_wh,
            G4, nullptr, gatePB, G4, (long long)BB * G4);
        lstm_kernel<<<dim3(BB, 4), 256>>>(gatePB, enc_b, encB + (long long)t * DH, 12);
    }

    // ---------------- decoder ----------------
    reset_state<<<(BB * DH + 255) / 256, 256>>>(1);
    for (int t = 0; t < LMAX; ++t) {
        attn_ctx<<<BB, 256>>>(dec_embed, attn_w, attn_b);

        // comb: chunk0 = e @ comb_w[0:1024], chunk1 = ctx @ comb_w[1024:2048]
        //       (K=1024 each, split 8 each -> 16 slabs)
        linearT<2, 8><<<dim3(8, 16), 256, smem128>>>(
            eB, DH, nullptr, 0, DH, comb_w, 8,
            ctxB, DH, DH, comb_w + (long long)DH * DH,
            DH, comb_b, combPB, DH, (long long)BB * DH);
        reduce_relu_kernel<<<dim3(BB, 4), 256>>>();

        // gates: chunk0 = inp @ dec_wx, chunk1 = h @ dec_wh  (split 8 each -> 16 slabs)
        linearT<2, 8><<<dim3(32, 16), 256, smem128>>>(
            inpB, DH, nullptr, 0, DH, dec_wx, 8,
            hB, DH, DH, dec_wh,
            G4, nullptr, gatePB, G4, (long long)BB * G4);
        lstm_kernel<<<dim3(BB, 4), 256>>>(gatePB, dec_b, nullptr, 16);

        // output projection with NEW h -> 4 partial slabs (Kc=256)
        linearT<4, 4><<<dim3(125, PROJ_SPLIT), 256, smem256>>>(
            hB, DH, nullptr, 0, DH, out_w, PROJ_SPLIT,
            hB, DH, DH, out_w,                 // chunk1 unused (split1 == 0)
            NV, nullptr, projPB, NV, (long long)BB * NV);

        // log-softmax: reduce slabs + bias, chunk stats, inline combine -> tok + lse
        logsm_phase1<<<dim3(BB, NLCH), 256>>>(out_b, out + (long long)t * NV,
                                              (long long)LMAX * NV, lseB + t * BB);
    }

    // deferred log-softmax normalization over the full output
    sub_lse_kernel<<<dim3(BB, LMAX), 256>>>(out);
}

// round 15
// speedup vs baseline: 3.2522x; 1.2218x over previous
#include <cuda_runtime.h>

#define BB    32
#define LMAX  64
#define EMB   512
#define DH    1024
#define G4    4096
#define NV    32000

#define PROJ_SPLIT 4
#define NLCH   16            // log-softmax chunks per row
#define LCHUNK (NV / NLCH)   // 2000
#define LCH4   (LCHUNK / 4)  // 500 float4s

// ---------------- device state (no allocation allowed) ----------------
__device__ float g_h[BB * DH];
__device__ float g_c[BB * DH];
__device__ float g_enc[BB * LMAX * DH];        // [b][l][d]
__device__ float g_e[BB * DH];                 // decoder embedding of current token
__device__ float g_ctx[BB * DH];               // attention context
__device__ float g_inp[BB * DH];               // relu(comb) = LSTM x-input
__device__ float g_combP[16 * BB * DH];        // comb partial slabs (2 x 8)
__device__ float g_gateP[32 * BB * G4];        // gate partial slabs (up to 32)
__device__ float g_projP[PROJ_SPLIT * BB * NV];// projection partial slabs
__device__ float g_pm[BB * NLCH];              // per-chunk max
__device__ int   g_pi[BB * NLCH];              // per-chunk argmax (global v index)
__device__ float g_ps[BB * NLCH];              // per-chunk sum exp(z - chunk max)
__device__ float g_lseAll[LMAX * BB];          // lse per (t, b) for deferred subtract
__device__ unsigned g_cnt[BB];                 // phase1 completion counters (self-reset)
__device__ int   g_tok[BB];

// ---------------- f32x2 packed-FMA helpers ----------------
__device__ __forceinline__ unsigned long long pk2(float x, float y) {
    unsigned long long r;
    asm("mov.b64 %0, {%1, %2};" : "=l"(r) : "r"(__float_as_uint(x)), "r"(__float_as_uint(y)));
    return r;
}
__device__ __forceinline__ void upk2(unsigned long long v, float& lo, float& hi) {
    unsigned a, b;
    asm("mov.b64 {%0, %1}, %2;" : "=r"(a), "=r"(b) : "l"(v));
    lo = __uint_as_float(a); hi = __uint_as_float(b);
}
__device__ __forceinline__ unsigned long long ff2(unsigned long long a, unsigned long long b,
                                                  unsigned long long c) {
    unsigned long long d;
    asm("fma.rn.f32x2 %0, %1, %2, %3;" : "=l"(d) : "l"(a), "l"(b), "l"(c));
    return d;
}

// ---------------------------------------------------------------------
// Skinny GEMM: OUT[b][j] = sum_k IN[b][k] * W[k][j]  (32 batch rows)
// - 2 columns/thread, U=8 weight-load batch (MLP), 256 threads:
//     64 threads span j (128 cols/block), 4 groups of 8 batch rows
// - blockIdx.y flat-indexes slabs of BOTH chunks: [0,split0) chunk0,
//   [split0, gridDim.y) chunk1; each slab writes a deterministic partial
// - input staged transposed in smem (stride 36, 16B-aligned batch pairs)
// - f32x2 accumulators over batch pairs; bias added only in slab 0
// - optional token-gather rows for chunk 0 (embedding lookup)
// ---------------------------------------------------------------------
#define UB 8
extern "C" __global__ void __launch_bounds__(256)
linear2(const float* __restrict__ in0, long long in0Stride,
        const int* __restrict__ tok0, int tok0Stride, int K0,
        const float* __restrict__ W0, int split0,
        const float* __restrict__ in1, long long in1Stride, int K1,
        const float* __restrict__ W1,
        int N, const float* __restrict__ bias,
        float* __restrict__ out, long long outRowStride,
        long long outSlabStride)
{
    extern __shared__ float s_in[];

    const int slab = blockIdx.y;
    const float* in; const float* W; const int* tok = nullptr;
    int tokStride = 0; long long inStride; int Kc, k0;
    if (slab < split0) {
        in = in0; W = W0; tok = tok0; tokStride = tok0Stride; inStride = in0Stride;
        Kc = K0 / split0; k0 = slab * Kc;
    } else {
        in = in1; W = W1; inStride = in1Stride;
        int split1 = gridDim.y - split0;
        Kc = K1 / split1; k0 = (slab - split0) * Kc;
    }

    const int tid = threadIdx.x;

    // stage input slice transposed: s_in[k*36 + b]
    for (int idx = tid; idx < BB * Kc; idx += 256) {
        int b = idx / Kc;
        int k = idx - b * Kc;
        long long row = tok ? (long long)tok[b * tokStride] * inStride
                            : (long long)b * inStride;
        s_in[(unsigned)k * 36u + b] = in[row + k0 + k];
    }
    __syncthreads();

    const int tj = tid & 63;
    const int bg = tid >> 6;
    const int b0 = bg * 8;
    const int jA = blockIdx.x * 128 + tj * 2;

    const float* Wp = W + (long long)k0 * N + jA;
    const float* sp = s_in + b0;

    unsigned long long acc[2][4];
#pragma unroll
    for (int j = 0; j < 2; ++j)
#pragma unroll
        for (int r = 0; r < 4; ++r) acc[j][r] = 0ull;

    for (int kb = 0; kb < Kc; kb += UB) {
        // batch-load UB weight rows (front-batched LDGs -> MLP = UB)
        float2 wv[UB];
#pragma unroll
        for (int u = 0; u < UB; ++u)
            wv[u] = *reinterpret_cast<const float2*>(Wp + (long long)u * N);
        Wp += (long long)UB * N;

#pragma unroll
        for (int u = 0; u < UB; ++u) {
            unsigned long long wa = pk2(wv[u].x, wv[u].x);
            unsigned long long wb = pk2(wv[u].y, wv[u].y);
            const ulonglong2* sr = reinterpret_cast<const ulonglong2*>(sp + u * 36);
            ulonglong2 p0 = sr[0];   // batch rows b0..b0+3
            ulonglong2 p1 = sr[1];   // batch rows b0+4..b0+7
            acc[0][0] = ff2(p0.x, wa, acc[0][0]);  acc[1][0] = ff2(p0.x, wb, acc[1][0]);
            acc[0][1] = ff2(p0.y, wa, acc[0][1]);  acc[1][1] = ff2(p0.y, wb, acc[1][1]);
            acc[0][2] = ff2(p1.x, wa, acc[0][2]);  acc[1][2] = ff2(p1.x, wb, acc[1][2]);
            acc[0][3] = ff2(p1.y, wa, acc[0][3]);  acc[1][3] = ff2(p1.y, wb, acc[1][3]);
        }
        sp += UB * 36;
    }

    float bj0 = 0.f, bj1 = 0.f;
    if (slab == 0 && bias) { bj0 = bias[jA]; bj1 = bias[jA + 1]; }

    float* ob = out + (long long)slab * outSlabStride;

#pragma unroll
    for (int r = 0; r < 4; ++r) {
        float xl, xh, yl, yh;
        upk2(acc[0][r], xl, xh); upk2(acc[1][r], yl, yh);
        float* r0 = ob + (long long)(b0 + 2 * r) * outRowStride + jA;
        float* r1 = r0 + outRowStride;
        *reinterpret_cast<float2*>(r0) = make_float2(xl + bj0, yl + bj1);
        *reinterpret_cast<float2*>(r1) = make_float2(xh + bj0, yh + bj1);
    }
}

// ---------------- LSTM pointwise: sum gate partials + bias, update h,c ----------------
template<int NP>
__global__ void __launch_bounds__(256)
lstm_kernel(const float* __restrict__ P, const float* __restrict__ bias,
            float* __restrict__ encOut)
{
    int b = blockIdx.x;
    int d = blockIdx.y * 256 + threadIdx.x;
    float gi = bias[d], gf = bias[DH + d], gg = bias[2 * DH + d], go = bias[3 * DH + d];
#pragma unroll
    for (int p = 0; p < NP; ++p) {
        const float* pb = P + (long long)p * BB * G4 + (long long)b * G4 + d;
        gi += pb[0]; gf += pb[DH]; gg += pb[2 * DH]; go += pb[3 * DH];
    }
    float iv = 1.f / (1.f + expf(-gi));
    float fv = 1.f / (1.f + expf(-gf));
    float gv = tanhf(gg);
    float ov = 1.f / (1.f + expf(-go));
    float cv = fv * g_c[b * DH + d] + iv * gv;
    float hv = ov * tanhf(cv);
    g_c[b * DH + d] = cv;
    g_h[b * DH + d] = hv;
    if (encOut) encOut[(long long)b * LMAX * DH + d] = hv;
}

// ---------------- decoder: embed gather + attention softmax + context ----------------
extern "C" __global__ void __launch_bounds__(512)
attn_ctx(const float* __restrict__ dec_embed,
         const float* __restrict__ attn_w,
         const float* __restrict__ attn_b)
{
    __shared__ float se[DH], sh[DH], sp[8 * 64], sw[64];
    __shared__ float s_max, s_inv;
    int b = blockIdx.x, tid = threadIdx.x;
    int tk = g_tok[b];
    for (int d = tid; d < DH; d += 512) {
        float ev = dec_embed[(long long)tk * DH + d];
        se[d] = ev;
        g_e[b * DH + d] = ev;
        sh[d] = g_h[b * DH + d];
    }
    __syncthreads();
    {
        int l = tid & 63, q = tid >> 6;                    // 8 k-slices of 256
        const float* src = (q < 4) ? (se + q * 256) : (sh + (q - 4) * 256);
        const float* wp  = attn_w + (long long)(q * 256) * 64 + l;
        float a = 0.f;
#pragma unroll 8
        for (int kk = 0; kk < 256; ++kk) a += src[kk] * wp[(long long)kk * 64];
        sp[q * 64 + l] = a;
    }
    __syncthreads();
    if (tid < 64) {
        float a = attn_b[tid];
#pragma unroll
        for (int q = 0; q < 8; ++q) a += sp[q * 64 + tid];
        sw[tid] = a;
    }
    __syncthreads();
    if (tid == 0) {
        float m = sw[0];
        for (int l = 1; l < 64; ++l) m = fmaxf(m, sw[l]);
        s_max = m;
    }
    __syncthreads();
    if (tid < 64) sw[tid] = expf(sw[tid] - s_max);
    __syncthreads();
    if (tid == 0) {
        float s = 0.f;
        for (int l = 0; l < 64; ++l) s += sw[l];
        s_inv = 1.f / s;
    }
    __syncthreads();
    if (tid < 64) sw[tid] *= s_inv;
    __syncthreads();
    const float* eb = g_enc + (long long)b * LMAX * DH;
    for (int d = tid; d < DH; d += 512) {
        float a = 0.f;
#pragma unroll 8
        for (int l = 0; l < 64; ++l) a += sw[l] * eb[(long long)l * DH + d];
        g_ctx[b * DH + d] = a;
    }
}

// ---------------- sum comb partials (bias already in slab 0) + relu ----------------
extern "C" __global__ void reduce_relu_kernel()
{
    int b = blockIdx.x;
    int d = blockIdx.y * 256 + threadIdx.x;
    float v = 0.f;
#pragma unroll
    for (int p = 0; p < 16; ++p) v += g_combP[(long long)p * BB * DH + b * DH + d];
    g_inp[b * DH + d] = fmaxf(v, 0.f);
}

// ---------------- log-softmax phase 1: slab-reduce + chunk stats + last-block combine ----
// Writes raw logits z to out; last block per batch row combines chunk stats into
// lse (stored for deferred subtraction) and argmax token. Deterministic: combine
// result is independent of block arrival order.
extern "C" __global__ void __launch_bounds__(256)
logsm_phase1(const float* __restrict__ bias, float* __restrict__ out,
             long long rowStride, float* __restrict__ lse_t)
{
    __shared__ float4 sz[LCH4];
    __shared__ float rm[256];
    __shared__ int   rix[256];
    __shared__ float rs[256];
    __shared__ int   sIsLast;
    int b = blockIdx.x, c = blockIdx.y, tid = threadIdx.x;
    int v0 = c * LCHUNK;
    const float4* bias4 = reinterpret_cast<const float4*>(bias + v0);
    float4* row4 = reinterpret_cast<float4*>(out + (long long)b * rowStride + v0);

    float m = -3.4e38f; int mi = 0;
    for (int v4 = tid; v4 < LCH4; v4 += 256) {
        float4 z = bias4[v4];
#pragma unroll
        for (int s = 0; s < PROJ_SPLIT; ++s) {
            float4 p = *reinterpret_cast<const float4*>(
                g_projP + (long long)s * BB * NV + (long long)b * NV + v0 + v4 * 4);
            z.x += p.x; z.y += p.y; z.z += p.z; z.w += p.w;
        }
        sz[v4] = z;
        row4[v4] = z;
        int gv = v0 + v4 * 4;
        if (z.x > m) { m = z.x; mi = gv; }
        if (z.y > m) { m = z.y; mi = gv + 1; }
        if (z.z > m) { m = z.z; mi = gv + 2; }
        if (z.w > m) { m = z.w; mi = gv + 3; }
    }
    rm[tid] = m; rix[tid] = mi;
    __syncthreads();
    for (int off = 128; off > 0; off >>= 1) {
        if (tid < off) {
            float ov = rm[tid + off]; int oi = rix[tid + off];
            if (ov > rm[tid] || (ov == rm[tid] && oi < rix[tid])) { rm[tid] = ov; rix[tid] = oi; }
        }
        __syncthreads();
    }
    float mb = rm[0]; int ib = rix[0];
    __syncthreads();

    float s = 0.f;
    for (int v4 = tid; v4 < LCH4; v4 += 256) {
        float4 z = sz[v4];
        s += expf(z.x - mb) + expf(z.y - mb) + expf(z.z - mb) + expf(z.w - mb);
    }
    rs[tid] = s;
    __syncthreads();
    for (int off = 128; off > 0; off >>= 1) {
        if (tid < off) rs[tid] += rs[tid + off];
        __syncthreads();
    }
    if (tid == 0) {
        g_pm[b * NLCH + c] = mb;
        g_pi[b * NLCH + c] = ib;
        g_ps[b * NLCH + c] = rs[0];
        __threadfence();
        unsigned prev = atomicAdd(&g_cnt[b], 1u);
        sIsLast = (prev == NLCH - 1);
    }
    __syncthreads();
    if (sIsLast && tid == 0) {
        __threadfence();
        float M = -3.4e38f;
        for (int k = 0; k < NLCH; ++k) M = fmaxf(M, g_pm[b * NLCH + k]);
        float S = 0.f; int idx = 0; bool found = false;
        for (int k = 0; k < NLCH; ++k) {
            S += g_ps[b * NLCH + k] * expf(g_pm[b * NLCH + k] - M);
            if (!found && g_pm[b * NLCH + k] == M) { idx = g_pi[b * NLCH + k]; found = true; }
        }
        lse_t[b] = M + logf(S);
        g_tok[b] = idx;
        g_cnt[b] = 0;              // self-reset for next step / next replay
    }
}

// ---------------- deferred: subtract lse from every output row ----------------
extern "C" __global__ void __launch_bounds__(256)
sub_lse_kernel(float* __restrict__ out)
{
    int b = blockIdx.x, t = blockIdx.y, tid = threadIdx.x;
    float lse = g_lseAll[t * BB + b];
    float4* row = reinterpret_cast<float4*>(out + ((long long)b * LMAX + t) * NV);
    for (int v = tid; v < NV / 4; v += 256) {
        float4 z = row[v];
        z.x -= lse; z.y -= lse; z.z -= lse; z.w -= lse;
        row[v] = z;
    }
}

// ---------------- reset h,c (and tokens for decoder start) ----------------
extern "C" __global__ void reset_state(int setTok)
{
    int i = blockIdx.x * blockDim.x + threadIdx.x;
    if (i < BB * DH) { g_h[i] = 0.f; g_c[i] = 0.f; }
    if (setTok && i < BB) g_tok[i] = 127;
    if (i < BB) g_cnt[i] = 0;
}

// ---------------------------------------------------------------------
extern "C" void kernel_launch(void* const* d_in, const int* in_sizes, int n_in,
                              void* d_out, int out_size)
{
    const int*   x         = (const int*)  d_in[0];
    const float* enc_embed = (const float*)d_in[1];
    const float* enc_wx    = (const float*)d_in[2];
    const float* enc_wh    = (const float*)d_in[3];
    const float* enc_b     = (const float*)d_in[4];
    const float* dec_embed = (const float*)d_in[5];
    const float* attn_w    = (const float*)d_in[6];
    const float* attn_b    = (const float*)d_in[7];
    const float* comb_w    = (const float*)d_in[8];
    const float* comb_b    = (const float*)d_in[9];
    const float* dec_wx    = (const float*)d_in[10];
    const float* dec_wh    = (const float*)d_in[11];
    const float* dec_b     = (const float*)d_in[12];
    const float* out_w     = (const float*)d_in[13];
    const float* out_b     = (const float*)d_in[14];
    float* out = (float*)d_out;

    float *hB, *encB, *eB, *ctxB, *inpB, *combPB, *gatePB, *projPB, *lseB;
    cudaGetSymbolAddress((void**)&hB,     g_h);
    cudaGetSymbolAddress((void**)&encB,   g_enc);
    cudaGetSymbolAddress((void**)&eB,     g_e);
    cudaGetSymbolAddress((void**)&ctxB,   g_ctx);
    cudaGetSymbolAddress((void**)&inpB,   g_inp);
    cudaGetSymbolAddress((void**)&combPB, g_combP);
    cudaGetSymbolAddress((void**)&gatePB, g_gateP);
    cudaGetSymbolAddress((void**)&projPB, g_projP);
    cudaGetSymbolAddress((void**)&lseB,   g_lseAll);

    (void)in_sizes; (void)n_in; (void)out_size;

    const int smem64  = 64  * 36 * 4;   // Kc = 64  (gates)
    const int smem128 = 128 * 36 * 4;   // Kc = 128 (comb)
    const int smem256 = 256 * 36 * 4;   // Kc = 256 (projection)

    // ---------------- encoder ----------------
    reset_state<<<(BB * DH + 255) / 256, 256>>>(0);
    for (int t = 0; t < LMAX; ++t) {
        // gates: chunk0 = embed[x[:,t]] @ enc_wx (K=512, split 8),
        //        chunk1 = h @ enc_wh            (K=1024, split 16) -> 24 slabs
        linear2<<<dim3(32, 24), 256, smem64>>>(
            enc_embed, EMB, x + t, LMAX, EMB, enc_wx, 8,
            hB, DH, DH, enc_wh,
            G4, nullptr, gatePB, G4, (long long)BB * G4);
        lstm_kernel<24><<<dim3(BB, 4), 256>>>(gatePB, enc_b, encB + (long long)t * DH);
    }

    // ---------------- decoder ----------------
    reset_state<<<(BB * DH + 255) / 256, 256>>>(1);
    for (int t = 0; t < LMAX; ++t) {
        attn_ctx<<<BB, 512>>>(dec_embed, attn_w, attn_b);

        // comb: chunk0 = e @ comb_w[0:1024], chunk1 = ctx @ comb_w[1024:2048]
        //       (K=1024 each, split 8 each -> 16 slabs)
        linear2<<<dim3(8, 16), 256, smem128>>>(
            eB, DH, nullptr, 0, DH, comb_w, 8,
            ctxB, DH, DH, comb_w + (long long)DH * DH,
            DH, comb_b, combPB, DH, (long long)BB * DH);
        reduce_relu_kernel<<<dim3(BB, 4), 256>>>();

        // gates: chunk0 = inp @ dec_wx, chunk1 = h @ dec_wh (split 16 each -> 32 slabs)
        linear2<<<dim3(32, 32), 256, smem64>>>(
            inpB, DH, nullptr, 0, DH, dec_wx, 16,
            hB, DH, DH, dec_wh,
            G4, nullptr, gatePB, G4, (long long)BB * G4);
        lstm_kernel<32><<<dim3(BB, 4), 256>>>(gatePB, dec_b, nullptr);

        // output projection with NEW h -> 4 partial slabs (Kc=256, 1000 blocks)
        linear2<<<dim3(250, PROJ_SPLIT), 256, smem256>>>(
            hB, DH, nullptr, 0, DH, out_w, PROJ_SPLIT,
            hB, DH, DH, out_w,                 // chunk1 unused (split1 == 0)
            NV, nullptr, projPB, NV, (long long)BB * NV);

        // log-softmax: reduce slabs + bias, chunk stats, inline combine -> tok + lse
        logsm_phase1<<<dim3(BB, NLCH), 256>>>(out_b, out + (long long)t * NV,
                                              (long long)LMAX * NV, lseB + t * BB);
    }

    // deferred log-softmax normalization over the full output
    sub_lse_kernel<<<dim3(BB, LMAX), 256>>>(out);
}